// round 11
// baseline (speedup 1.0000x reference)
#include <cuda_runtime.h>
#include <cuda_bf16.h>
#include <math.h>

#define BB 128
#define DD 20
#define WW 8
#define IN_DIM 64
#define HID 4096
#define NE 4
#define CHUNK 48
#define NCHUNK 3          // ceil(128/48) chunks per expert max

// ---------------- scratch (no allocations allowed) ----------------
__device__ float g_flat[BB * IN_DIM];
__device__ float g_H[BB * HID];      // hidden activations (2 MB)
__device__ float g_O[BB * HID];      // layer-2 logits (raw, pre-softmax)
__device__ int   g_expert[BB];
__device__ int   g_list[NE * BB];
__device__ int   g_cnt[NE];

// ---------------- packed f32x2 helpers (sm_103a FFMA2) ----------------
__device__ __forceinline__ unsigned long long pack2(float lo, float hi) {
    unsigned long long r;
    asm("mov.b64 %0, {%1, %2};" : "=l"(r) : "f"(lo), "f"(hi));
    return r;
}
__device__ __forceinline__ void unpack2(unsigned long long v, float& lo, float& hi) {
    asm("mov.b64 {%0, %1}, %2;" : "=f"(lo), "=f"(hi) : "l"(v));
}
__device__ __forceinline__ unsigned long long fma2(unsigned long long a,
                                                   unsigned long long b,
                                                   unsigned long long c) {
    unsigned long long d;
    asm("fma.rn.f32x2 %0, %1, %2, %3;" : "=l"(d) : "l"(a), "l"(b), "l"(c));
    return d;
}

// ---------------- conv stack: (B,D,1,8,8) -> flat (B,64) ----------------
__global__ void conv_kernel(const float* __restrict__ input,
                            const float* __restrict__ c1w,
                            const float* __restrict__ c1b,
                            const float* __restrict__ c2w,
                            const float* __restrict__ c2b) {
    int b = blockIdx.x;
    int tid = threadIdx.x;                      // 128 threads
    __shared__ float xs[DD * 64];               // input slab (d,h,w)
    __shared__ float y1s[DD * 64];              // one conv1 channel
    __shared__ float accs[128];
    __shared__ float w1s[270];
    __shared__ float b1s[10];
    __shared__ float w2s[1800];

    for (int r = tid; r < DD * 64; r += 128) xs[r] = input[b * DD * 64 + r];
    for (int r = tid; r < 270; r += 128) w1s[r] = c1w[r];
    if (tid < 10) b1s[tid] = c1b[tid];
    for (int r = tid; r < 1800; r += 128) w2s[r] = c2w[r];
    __syncthreads();

    float acc2 = 0.0f;
    int hw = tid & 63, half = tid >> 6;
    int oh = hw >> 3, ow = hw & 7;

    for (int o = 0; o < 10; o++) {
        // conv1 channel o with padding 1 in (d,h,w), ReLU
        for (int r = tid; r < DD * 64; r += 128) {
            int d = r >> 6, p = r & 63, h = p >> 3, w = p & 7;
            float v = b1s[o];
            #pragma unroll
            for (int kd = 0; kd < 3; kd++) {
                int dd = d + kd - 1;
                if (dd < 0 || dd >= DD) continue;
                #pragma unroll
                for (int kh = 0; kh < 3; kh++) {
                    int hh = h + kh - 1;
                    if (hh < 0 || hh >= 8) continue;
                    #pragma unroll
                    for (int kw = 0; kw < 3; kw++) {
                        int ww2 = w + kw - 1;
                        if (ww2 < 0 || ww2 >= 8) continue;
                        v += xs[dd * 64 + hh * 8 + ww2] * w1s[o * 27 + kd * 9 + kh * 3 + kw];
                    }
                }
            }
            y1s[r] = fmaxf(v, 0.0f);
        }
        __syncthreads();
        // conv2 partial: kernel covers full depth (pad 0), (3,3) spatial pad 1
        {
            int kd0 = half * 10;
            for (int kd = kd0; kd < kd0 + 10; kd++) {
                #pragma unroll
                for (int kh = 0; kh < 3; kh++) {
                    int hh = oh + kh - 1;
                    if (hh < 0 || hh >= 8) continue;
                    #pragma unroll
                    for (int kw = 0; kw < 3; kw++) {
                        int ww2 = ow + kw - 1;
                        if (ww2 < 0 || ww2 >= 8) continue;
                        acc2 += y1s[kd * 64 + hh * 8 + ww2] * w2s[o * 180 + kd * 9 + kh * 3 + kw];
                    }
                }
            }
        }
        __syncthreads();
    }
    accs[tid] = acc2;
    __syncthreads();
    if (tid < 64) {
        float v = accs[tid] + accs[tid + 64] + c2b[0];
        g_flat[b * 64 + tid] = fmaxf(v, 0.0f);
    }
}

// ---------------- gating: top-1 argmax, lists, aux loss ----------------
__global__ void gate_kernel(const float* __restrict__ w_gate,
                            float* __restrict__ aux_out, int write_aux) {
    __shared__ int cnt_s[NE];
    int b = threadIdx.x;                        // 128 threads, 1 block
    if (b < NE) cnt_s[b] = 0;
    __syncthreads();

    float lg[NE] = {0.f, 0.f, 0.f, 0.f};
    for (int i = 0; i < IN_DIM; i++) {
        float f = g_flat[b * IN_DIM + i];
        #pragma unroll
        for (int e = 0; e < NE; e++) lg[e] += f * w_gate[i * NE + e];
    }
    int best = 0; float bv = lg[0];
    #pragma unroll
    for (int e = 1; e < NE; e++) if (lg[e] > bv) { bv = lg[e]; best = e; }
    g_expert[b] = best;
    int pos = atomicAdd(&cnt_s[best], 1);
    g_list[best * BB + pos] = b;
    __syncthreads();
    if (b < NE) g_cnt[b] = cnt_s[b];
    if (b == 0) {
        float m = 0.f;
        for (int e = 0; e < NE; e++) m += (float)cnt_s[e];
        m *= 0.25f;
        float var = 0.f;
        for (int e = 0; e < NE; e++) {
            float d = (float)cnt_s[e] - m;
            var += d * d;
        }
        var *= (1.0f / 3.0f);                   // ddof=1
        float aux = 2.0f * (var / (m * m + 1e-10f)) * 1e-2f;
        if (write_aux) aux_out[0] = aux;
    }
}

// ---------------- expert layer 1: H = relu(flat @ w1[e] + b1[e]) ----------------
__global__ void expert_l1(const float* __restrict__ w1,
                          const float* __restrict__ b1) {
    int b = blockIdx.x;
    int tid = threadIdx.x;                      // 128 threads
    __shared__ float fs[IN_DIM];
    if (tid < IN_DIM) fs[tid] = g_flat[b * IN_DIM + tid];
    __syncthreads();
    int e = g_expert[b];
    const float* w1e = w1 + (size_t)e * IN_DIM * HID + tid;
    float acc[32];
    #pragma unroll
    for (int jj = 0; jj < 32; jj++) acc[jj] = b1[e * HID + jj * 128 + tid];
    for (int i = 0; i < IN_DIM; i++) {
        float f = fs[i];
        const float* row = w1e + (size_t)i * HID;
        #pragma unroll
        for (int jj = 0; jj < 32; jj++) acc[jj] = fmaf(f, row[jj * 128], acc[jj]);
    }
    #pragma unroll
    for (int jj = 0; jj < 32; jj++)
        g_H[(size_t)b * HID + jj * 128 + tid] = fmaxf(acc[jj], 0.0f);
}

// ------ expert layer 2: O = H @ w2[e] + b2[e] (grouped, f32x2, dbl-buffered,
//        8-deep w2 prefetch for DRAM latency coverage) ----
__global__ void __launch_bounds__(128) expert_l2(const float* __restrict__ w2,
                                                 const float* __restrict__ b2) {
    int e = blockIdx.y / NCHUNK;
    int chunk = blockIdx.y % NCHUNK;
    int cnt = g_cnt[e];
    int s0 = chunk * CHUNK;
    if (s0 >= cnt) return;
    int ns = min(CHUNK, cnt - s0);
    int j = blockIdx.x * 128 + threadIdx.x;

    __shared__ int sid[CHUNK];
    __shared__ __align__(8) float hs[2][32][CHUNK + 2];   // double-buffered tiles

    if (threadIdx.x < CHUNK)
        sid[threadIdx.x] = (threadIdx.x < ns) ? g_list[e * BB + s0 + threadIdx.x] : 0;
    __syncthreads();

    unsigned long long acc[CHUNK / 2];
    #pragma unroll
    for (int p = 0; p < CHUNK / 2; p++) acc[p] = 0ULL;

    const float* w2e = w2 + (size_t)e * HID * HID + j;
    const int NTILES = HID / 32;

    // vectorized tile fill: CHUNK samples x 8 float4 (=32 h) each
    auto fill_tile = [&](int buf, int h0) {
        for (int idx = threadIdx.x; idx < CHUNK * 8; idx += 128) {
            int si = idx >> 3, q = idx & 7;     // q: which float4 within 32 h
            float4 v = make_float4(0.f, 0.f, 0.f, 0.f);
            if (si < ns)
                v = *reinterpret_cast<const float4*>(
                        &g_H[(size_t)sid[si] * HID + h0 + q * 4]);
            int hh = q * 4;
            hs[buf][hh + 0][si] = v.x;
            hs[buf][hh + 1][si] = v.y;
            hs[buf][hh + 2][si] = v.z;
            hs[buf][hh + 3][si] = v.w;
        }
    };

    // prologue: fill buffer 0
    fill_tile(0, 0);
    __syncthreads();

    for (int t = 0; t < NTILES; t++) {
        int cur = t & 1, nxt = cur ^ 1;
        // issue next-tile loads first; they drain while we do FMAs
        if (t + 1 < NTILES) fill_tile(nxt, (t + 1) * 32);
        const float* wp = w2e + (size_t)(t * 32) * HID;
        // 4 groups of 8: batch-load 8 w values (MLP=8), then FMA burst
        #pragma unroll
        for (int g = 0; g < 4; g++) {
            float wv[8];
            #pragma unroll
            for (int u = 0; u < 8; u++)
                wv[u] = wp[(size_t)(g * 8 + u) * HID];
            #pragma unroll
            for (int u = 0; u < 8; u++) {
                unsigned long long w2k = pack2(wv[u], wv[u]);
                const unsigned long long* hp =
                    reinterpret_cast<const unsigned long long*>(&hs[cur][g * 8 + u][0]);
                #pragma unroll
                for (int p = 0; p < CHUNK / 2; p++)
                    acc[p] = fma2(hp[p], w2k, acc[p]);
            }
        }
        __syncthreads();   // next buffer filled AND cur fully consumed
    }
    float bb2 = b2[e * HID + j];
    #pragma unroll
    for (int p = 0; p < CHUNK / 2; p++) {
        float lo, hi;
        unpack2(acc[p], lo, hi);
        int si0 = 2 * p, si1 = 2 * p + 1;
        if (si0 < ns) g_O[(size_t)sid[si0] * HID + j] = lo + bb2;
        if (si1 < ns) g_O[(size_t)sid[si1] * HID + j] = hi + bb2;
    }
}

// ------- fused softmax + per-sample 64x64 transform + sigmoid -------
// softmax normalizer is a single scalar per sample (softmax over the whole
// 4096-wide row), and the transform is linear in y, so:
//   out = sigmoid( (1/sum) * [exp(v - max)] @ inp )
__global__ void transform_kernel(const float* __restrict__ input,
                                 float* __restrict__ out) {
    int b = blockIdx.x;
    int tid = threadIdx.x;                      // 256 threads
    __shared__ float ys[64 * 65];               // exp(v-max), row-padded (stride 65)
    __shared__ float ins[DD * 64];
    __shared__ float red[8];

    // pass 1: load raw logits, block max
    float v[16];
    float mx = -3.4e38f;
    #pragma unroll
    for (int k = 0; k < 16; k++) {
        v[k] = g_O[(size_t)b * HID + k * 256 + tid];
        mx = fmaxf(mx, v[k]);
    }
    #pragma unroll
    for (int o = 16; o; o >>= 1) mx = fmaxf(mx, __shfl_xor_sync(0xffffffffu, mx, o));
    if ((tid & 31) == 0) red[tid >> 5] = mx;
    __syncthreads();
    mx = red[0];
    #pragma unroll
    for (int k = 1; k < 8; k++) mx = fmaxf(mx, red[k]);
    __syncthreads();

    // pass 2: exp into smem (transposed layout i*65+jn), block sum
    float sum = 0.f;
    #pragma unroll
    for (int k = 0; k < 16; k++) {
        float e = expf(v[k] - mx);
        sum += e;
        int idx = k * 256 + tid;
        int i = idx >> 6, jn = idx & 63;
        ys[i * 65 + jn] = e;
    }
    #pragma unroll
    for (int o = 16; o; o >>= 1) sum += __shfl_xor_sync(0xffffffffu, sum, o);
    if ((tid & 31) == 0) red[tid >> 5] = sum;

    for (int idx = tid; idx < DD * 64; idx += 256)
        ins[idx] = input[b * DD * 64 + idx];
    __syncthreads();
    sum = 0.f;
    #pragma unroll
    for (int k = 0; k < 8; k++) sum += red[k];
    float inv = 1.0f / sum;

    // pass 3: transform rows, scale by inv, sigmoid
    for (int item = tid; item < DD * 64; item += 256) {
        int d = item >> 6, i = item & 63;
        float accv = 0.f;
        #pragma unroll 8
        for (int jn = 0; jn < 64; jn++)
            accv = fmaf(ys[i * 65 + jn], ins[d * 64 + jn], accv);
        accv *= inv;
        out[b * DD * 64 + item] = 1.0f / (1.0f + expf(-accv));
    }
}

// ---------------- launch ----------------
extern "C" void kernel_launch(void* const* d_in, const int* in_sizes, int n_in,
                              void* d_out, int out_size) {
    const float* input  = (const float*)d_in[0];
    const float* c1w    = (const float*)d_in[1];
    const float* c1b    = (const float*)d_in[2];
    const float* c2w    = (const float*)d_in[3];
    const float* c2b    = (const float*)d_in[4];
    const float* w_gate = (const float*)d_in[5];
    const float* w1     = (const float*)d_in[6];
    const float* b1     = (const float*)d_in[7];
    const float* w2     = (const float*)d_in[8];
    const float* b2     = (const float*)d_in[9];
    float* out = (float*)d_out;

    int main_elems = BB * DD * IN_DIM;          // 163840
    int write_aux = (out_size > main_elems) ? 1 : 0;

    conv_kernel<<<BB, 128>>>(input, c1w, c1b, c2w, c2b);
    gate_kernel<<<1, 128>>>(w_gate, out + main_elems, write_aux);
    expert_l1<<<BB, 128>>>(w1, b1);
    dim3 g2(HID / 128, NE * NCHUNK);
    expert_l2<<<g2, 128>>>(w2, b2);
    transform_kernel<<<BB, 256>>>(input, out);
}

// round 15
// speedup vs baseline: 3.7109x; 3.7109x over previous
#include <cuda_runtime.h>
#include <cuda_bf16.h>
#include <math.h>

#define BB 128
#define DD 20
#define WW 8
#define IN_DIM 64
#define HID 4096
#define NE 4
#define CHUNK 48
#define NCHUNK 3          // ceil(128/48) chunks per expert max
#define KS 8              // K-split factor for expert_l2
#define SEG (HID / KS)    // 512 h-rows per split
#define L1SPLIT 4         // j-split factor for expert_l1
#define L1COLS (HID / L1SPLIT)   // 1024 columns per l1 block

// ---------------- scratch (no allocations allowed) ----------------
__device__ float g_flat[BB * IN_DIM];
__device__ float g_H[BB * HID];               // hidden activations (2 MB)
__device__ float g_part[KS][BB][HID];         // layer-2 partial sums (16 MB)
__device__ int   g_expert[BB];
__device__ int   g_list[NE * BB];
__device__ int   g_cnt[NE];

// ---------------- packed f32x2 helpers (sm_103a FFMA2) ----------------
__device__ __forceinline__ unsigned long long pack2(float lo, float hi) {
    unsigned long long r;
    asm("mov.b64 %0, {%1, %2};" : "=l"(r) : "f"(lo), "f"(hi));
    return r;
}
__device__ __forceinline__ void unpack2(unsigned long long v, float& lo, float& hi) {
    asm("mov.b64 {%0, %1}, %2;" : "=f"(lo), "=f"(hi) : "l"(v));
}
__device__ __forceinline__ unsigned long long fma2(unsigned long long a,
                                                   unsigned long long b,
                                                   unsigned long long c) {
    unsigned long long d;
    asm("fma.rn.f32x2 %0, %1, %2, %3;" : "=l"(d) : "l"(a), "l"(b), "l"(c));
    return d;
}

// ---------------- conv stack: (B,D,1,8,8) -> flat (B,64) ----------------
__global__ void conv_kernel(const float* __restrict__ input,
                            const float* __restrict__ c1w,
                            const float* __restrict__ c1b,
                            const float* __restrict__ c2w,
                            const float* __restrict__ c2b) {
    int b = blockIdx.x;
    int tid = threadIdx.x;                      // 128 threads
    __shared__ float xs[DD * 64];               // input slab (d,h,w)
    __shared__ float y1s[DD * 64];              // one conv1 channel
    __shared__ float accs[128];
    __shared__ float w1s[270];
    __shared__ float b1s[10];
    __shared__ float w2s[1800];

    for (int r = tid; r < DD * 64; r += 128) xs[r] = input[b * DD * 64 + r];
    for (int r = tid; r < 270; r += 128) w1s[r] = c1w[r];
    if (tid < 10) b1s[tid] = c1b[tid];
    for (int r = tid; r < 1800; r += 128) w2s[r] = c2w[r];
    __syncthreads();

    float acc2 = 0.0f;
    int hw = tid & 63, half = tid >> 6;
    int oh = hw >> 3, ow = hw & 7;

    for (int o = 0; o < 10; o++) {
        // conv1 channel o with padding 1 in (d,h,w), ReLU
        for (int r = tid; r < DD * 64; r += 128) {
            int d = r >> 6, p = r & 63, h = p >> 3, w = p & 7;
            float v = b1s[o];
            #pragma unroll
            for (int kd = 0; kd < 3; kd++) {
                int dd = d + kd - 1;
                if (dd < 0 || dd >= DD) continue;
                #pragma unroll
                for (int kh = 0; kh < 3; kh++) {
                    int hh = h + kh - 1;
                    if (hh < 0 || hh >= 8) continue;
                    #pragma unroll
                    for (int kw = 0; kw < 3; kw++) {
                        int ww2 = w + kw - 1;
                        if (ww2 < 0 || ww2 >= 8) continue;
                        v += xs[dd * 64 + hh * 8 + ww2] * w1s[o * 27 + kd * 9 + kh * 3 + kw];
                    }
                }
            }
            y1s[r] = fmaxf(v, 0.0f);
        }
        __syncthreads();
        // conv2 partial: kernel covers full depth (pad 0), (3,3) spatial pad 1
        {
            int kd0 = half * 10;
            for (int kd = kd0; kd < kd0 + 10; kd++) {
                #pragma unroll
                for (int kh = 0; kh < 3; kh++) {
                    int hh = oh + kh - 1;
                    if (hh < 0 || hh >= 8) continue;
                    #pragma unroll
                    for (int kw = 0; kw < 3; kw++) {
                        int ww2 = ow + kw - 1;
                        if (ww2 < 0 || ww2 >= 8) continue;
                        acc2 += y1s[kd * 64 + hh * 8 + ww2] * w2s[o * 180 + kd * 9 + kh * 3 + kw];
                    }
                }
            }
        }
        __syncthreads();
    }
    accs[tid] = acc2;
    __syncthreads();
    if (tid < 64) {
        float v = accs[tid] + accs[tid + 64] + c2b[0];
        g_flat[b * 64 + tid] = fmaxf(v, 0.0f);
    }
}

// ---------------- gating: top-1 argmax, lists, aux loss ----------------
__global__ void gate_kernel(const float* __restrict__ w_gate,
                            float* __restrict__ aux_out, int write_aux) {
    __shared__ int cnt_s[NE];
    int b = threadIdx.x;                        // 128 threads, 1 block
    if (b < NE) cnt_s[b] = 0;
    __syncthreads();

    float lg[NE] = {0.f, 0.f, 0.f, 0.f};
    for (int i = 0; i < IN_DIM; i++) {
        float f = g_flat[b * IN_DIM + i];
        #pragma unroll
        for (int e = 0; e < NE; e++) lg[e] += f * w_gate[i * NE + e];
    }
    int best = 0; float bv = lg[0];
    #pragma unroll
    for (int e = 1; e < NE; e++) if (lg[e] > bv) { bv = lg[e]; best = e; }
    g_expert[b] = best;
    int pos = atomicAdd(&cnt_s[best], 1);
    g_list[best * BB + pos] = b;
    __syncthreads();
    if (b < NE) g_cnt[b] = cnt_s[b];
    if (b == 0) {
        float m = 0.f;
        for (int e = 0; e < NE; e++) m += (float)cnt_s[e];
        m *= 0.25f;
        float var = 0.f;
        for (int e = 0; e < NE; e++) {
            float d = (float)cnt_s[e] - m;
            var += d * d;
        }
        var *= (1.0f / 3.0f);                   // ddof=1
        float aux = 2.0f * (var / (m * m + 1e-10f)) * 1e-2f;
        if (write_aux) aux_out[0] = aux;
    }
}

// --------- expert layer 1 (j-split): H = relu(flat @ w1[e] + b1[e]) ----------
// grid = (BB, L1SPLIT): 512 blocks instead of 128 -> 4x occupancy.
__global__ void expert_l1(const float* __restrict__ w1,
                          const float* __restrict__ b1) {
    int b = blockIdx.x;
    int j0 = blockIdx.y * L1COLS;
    int tid = threadIdx.x;                      // 128 threads
    __shared__ float fs[IN_DIM];
    if (tid < IN_DIM) fs[tid] = g_flat[b * IN_DIM + tid];
    __syncthreads();
    int e = g_expert[b];
    const float* w1e = w1 + (size_t)e * IN_DIM * HID + j0 + tid;
    float acc[L1COLS / 128];
    #pragma unroll
    for (int jj = 0; jj < L1COLS / 128; jj++)
        acc[jj] = b1[e * HID + j0 + jj * 128 + tid];
    for (int i = 0; i < IN_DIM; i++) {
        float f = fs[i];
        const float* row = w1e + (size_t)i * HID;
        #pragma unroll
        for (int jj = 0; jj < L1COLS / 128; jj++)
            acc[jj] = fmaf(f, row[jj * 128], acc[jj]);
    }
    #pragma unroll
    for (int jj = 0; jj < L1COLS / 128; jj++)
        g_H[(size_t)b * HID + j0 + jj * 128 + tid] = fmaxf(acc[jj], 0.0f);
}

// ------ expert layer 2 (K-split): partial[ks] = H[:, seg] @ w2[e][seg, :] ------
// grid = (HID/128, NE*NCHUNK, KS). Each block covers 128 j-columns x one
// 512-row h-segment for one (expert, sample-chunk). 8x more active blocks
// than the unsplit version -> covers DRAM latency via occupancy.
__global__ void __launch_bounds__(128) expert_l2(const float* __restrict__ w2) {
    int e = blockIdx.y / NCHUNK;
    int chunk = blockIdx.y % NCHUNK;
    int ks = blockIdx.z;
    int cnt = g_cnt[e];
    int s0 = chunk * CHUNK;
    if (s0 >= cnt) return;
    int ns = min(CHUNK, cnt - s0);
    int j = blockIdx.x * 128 + threadIdx.x;

    __shared__ int sid[CHUNK];
    __shared__ __align__(8) float hs[2][32][CHUNK + 2];   // double-buffered tiles

    if (threadIdx.x < CHUNK)
        sid[threadIdx.x] = (threadIdx.x < ns) ? g_list[e * BB + s0 + threadIdx.x] : 0;
    __syncthreads();

    unsigned long long acc[CHUNK / 2];
    #pragma unroll
    for (int p = 0; p < CHUNK / 2; p++) acc[p] = 0ULL;

    const float* w2e = w2 + (size_t)e * HID * HID + j;
    const int hbase = ks * SEG;
    const int NTILES = SEG / 32;                // 16

    // vectorized tile fill: CHUNK samples x 8 float4 (=32 h) each
    auto fill_tile = [&](int buf, int h0) {
        for (int idx = threadIdx.x; idx < CHUNK * 8; idx += 128) {
            int si = idx >> 3, q = idx & 7;     // q: which float4 within 32 h
            float4 v = make_float4(0.f, 0.f, 0.f, 0.f);
            if (si < ns)
                v = *reinterpret_cast<const float4*>(
                        &g_H[(size_t)sid[si] * HID + h0 + q * 4]);
            int hh = q * 4;
            hs[buf][hh + 0][si] = v.x;
            hs[buf][hh + 1][si] = v.y;
            hs[buf][hh + 2][si] = v.z;
            hs[buf][hh + 3][si] = v.w;
        }
    };

    // prologue: fill buffer 0
    fill_tile(0, hbase);
    __syncthreads();

    for (int t = 0; t < NTILES; t++) {
        int cur = t & 1, nxt = cur ^ 1;
        // issue next-tile loads first; they drain while we do FMAs
        if (t + 1 < NTILES) fill_tile(nxt, hbase + (t + 1) * 32);
        const float* wp = w2e + (size_t)(hbase + t * 32) * HID;
        // 4 groups of 8: batch-load 8 w values (MLP=8), then FMA burst
        #pragma unroll
        for (int g = 0; g < 4; g++) {
            float wv[8];
            #pragma unroll
            for (int u = 0; u < 8; u++)
                wv[u] = wp[(size_t)(g * 8 + u) * HID];
            #pragma unroll
            for (int u = 0; u < 8; u++) {
                unsigned long long w2k = pack2(wv[u], wv[u]);
                const unsigned long long* hp =
                    reinterpret_cast<const unsigned long long*>(&hs[cur][g * 8 + u][0]);
                #pragma unroll
                for (int p = 0; p < CHUNK / 2; p++)
                    acc[p] = fma2(hp[p], w2k, acc[p]);
            }
        }
        __syncthreads();   // next buffer filled AND cur fully consumed
    }
    #pragma unroll
    for (int p = 0; p < CHUNK / 2; p++) {
        float lo, hi;
        unpack2(acc[p], lo, hi);
        int si0 = 2 * p, si1 = 2 * p + 1;
        if (si0 < ns) g_part[ks][sid[si0]][j] = lo;
        if (si1 < ns) g_part[ks][sid[si1]][j] = hi;
    }
}

// --- fused K-split reduce + bias + softmax + 64x64 transform + sigmoid ---
// softmax normalizer is a single scalar per sample, transform is linear:
//   out = sigmoid( (1/sum) * [exp(v - max)] @ inp )
__global__ void transform_kernel(const float* __restrict__ input,
                                 const float* __restrict__ b2,
                                 float* __restrict__ out) {
    int b = blockIdx.x;
    int tid = threadIdx.x;                      // 256 threads
    __shared__ float ys[64 * 65];               // exp(v-max), row-padded (stride 65)
    __shared__ float ins[DD * 64];
    __shared__ float red[8];

    int e = g_expert[b];
    const float* b2e = b2 + e * HID;

    // pass 1: reduce KS partials + bias, block max
    float v[16];
    float mx = -3.4e38f;
    #pragma unroll
    for (int k = 0; k < 16; k++) {
        int idx = k * 256 + tid;
        float s = b2e[idx];
        #pragma unroll
        for (int ks = 0; ks < KS; ks++) s += g_part[ks][b][idx];
        v[k] = s;
        mx = fmaxf(mx, s);
    }
    #pragma unroll
    for (int o = 16; o; o >>= 1) mx = fmaxf(mx, __shfl_xor_sync(0xffffffffu, mx, o));
    if ((tid & 31) == 0) red[tid >> 5] = mx;
    __syncthreads();
    mx = red[0];
    #pragma unroll
    for (int k = 1; k < 8; k++) mx = fmaxf(mx, red[k]);
    __syncthreads();

    // pass 2: exp into smem (transposed layout i*65+jn), block sum
    float sum = 0.f;
    #pragma unroll
    for (int k = 0; k < 16; k++) {
        float ev = expf(v[k] - mx);
        sum += ev;
        int idx = k * 256 + tid;
        int i = idx >> 6, jn = idx & 63;
        ys[i * 65 + jn] = ev;
    }
    #pragma unroll
    for (int o = 16; o; o >>= 1) sum += __shfl_xor_sync(0xffffffffu, sum, o);
    if ((tid & 31) == 0) red[tid >> 5] = sum;

    for (int idx = tid; idx < DD * 64; idx += 256)
        ins[idx] = input[b * DD * 64 + idx];
    __syncthreads();
    sum = 0.f;
    #pragma unroll
    for (int k = 0; k < 8; k++) sum += red[k];
    float inv = 1.0f / sum;

    // pass 3: transform rows, scale by inv, sigmoid
    for (int item = tid; item < DD * 64; item += 256) {
        int d = item >> 6, i = item & 63;
        float accv = 0.f;
        #pragma unroll 8
        for (int jn = 0; jn < 64; jn++)
            accv = fmaf(ys[i * 65 + jn], ins[d * 64 + jn], accv);
        accv *= inv;
        out[b * DD * 64 + item] = 1.0f / (1.0f + expf(-accv));
    }
}

// ---------------- launch ----------------
extern "C" void kernel_launch(void* const* d_in, const int* in_sizes, int n_in,
                              void* d_out, int out_size) {
    const float* input  = (const float*)d_in[0];
    const float* c1w    = (const float*)d_in[1];
    const float* c1b    = (const float*)d_in[2];
    const float* c2w    = (const float*)d_in[3];
    const float* c2b    = (const float*)d_in[4];
    const float* w_gate = (const float*)d_in[5];
    const float* w1     = (const float*)d_in[6];
    const float* b1     = (const float*)d_in[7];
    const float* w2     = (const float*)d_in[8];
    const float* b2     = (const float*)d_in[9];
    float* out = (float*)d_out;

    int main_elems = BB * DD * IN_DIM;          // 163840
    int write_aux = (out_size > main_elems) ? 1 : 0;

    conv_kernel<<<BB, 128>>>(input, c1w, c1b, c2w, c2b);
    gate_kernel<<<1, 128>>>(w_gate, out + main_elems, write_aux);
    dim3 g1(BB, L1SPLIT);
    expert_l1<<<g1, 128>>>(w1, b1);
    dim3 g2(HID / 128, NE * NCHUNK, KS);
    expert_l2<<<g2, 128>>>(w2);
    transform_kernel<<<BB, 256>>>(input, b2, out);
}

// round 16
// speedup vs baseline: 3.8234x; 1.0303x over previous
#include <cuda_runtime.h>
#include <cuda_bf16.h>
#include <math.h>

#define BB 128
#define DD 20
#define WW 8
#define IN_DIM 64
#define HID 4096
#define NE 4
#define CHUNK 16          // samples per expert_l2 block
#define NCHUNK 8          // 16*8 = 128 covers full single-expert collapse
#define KS 16             // K-split factor for expert_l2
#define SEG (HID / KS)    // 256 h-rows per split
#define JBLK 512          // j-columns per expert_l2 block (4 per thread)
#define L1SPLIT 4         // j-split factor for expert_l1
#define L1COLS (HID / L1SPLIT)   // 1024 columns per l1 block

// ---------------- scratch (no allocations allowed) ----------------
__device__ float g_flat[BB * IN_DIM];
__device__ float g_H[BB * HID];               // hidden activations (2 MB)
__device__ float g_part[KS][BB][HID];         // layer-2 partial sums (32 MB)
__device__ int   g_expert[BB];
__device__ int   g_list[NE * BB];
__device__ int   g_cnt[NE];

// ---------------- packed f32x2 helpers (sm_103a FFMA2) ----------------
__device__ __forceinline__ unsigned long long pack2(float lo, float hi) {
    unsigned long long r;
    asm("mov.b64 %0, {%1, %2};" : "=l"(r) : "f"(lo), "f"(hi));
    return r;
}
__device__ __forceinline__ void unpack2(unsigned long long v, float& lo, float& hi) {
    asm("mov.b64 {%0, %1}, %2;" : "=f"(lo), "=f"(hi) : "l"(v));
}
__device__ __forceinline__ unsigned long long fma2(unsigned long long a,
                                                   unsigned long long b,
                                                   unsigned long long c) {
    unsigned long long d;
    asm("fma.rn.f32x2 %0, %1, %2, %3;" : "=l"(d) : "l"(a), "l"(b), "l"(c));
    return d;
}

// ---------------- conv stack: (B,D,1,8,8) -> flat (B,64) ----------------
__global__ void conv_kernel(const float* __restrict__ input,
                            const float* __restrict__ c1w,
                            const float* __restrict__ c1b,
                            const float* __restrict__ c2w,
                            const float* __restrict__ c2b) {
    int b = blockIdx.x;
    int tid = threadIdx.x;                      // 128 threads
    __shared__ float xs[DD * 64];
    __shared__ float y1s[DD * 64];
    __shared__ float accs[128];
    __shared__ float w1s[270];
    __shared__ float b1s[10];
    __shared__ float w2s[1800];

    for (int r = tid; r < DD * 64; r += 128) xs[r] = input[b * DD * 64 + r];
    for (int r = tid; r < 270; r += 128) w1s[r] = c1w[r];
    if (tid < 10) b1s[tid] = c1b[tid];
    for (int r = tid; r < 1800; r += 128) w2s[r] = c2w[r];
    __syncthreads();

    float acc2 = 0.0f;
    int hw = tid & 63, half = tid >> 6;
    int oh = hw >> 3, ow = hw & 7;

    for (int o = 0; o < 10; o++) {
        for (int r = tid; r < DD * 64; r += 128) {
            int d = r >> 6, p = r & 63, h = p >> 3, w = p & 7;
            float v = b1s[o];
            #pragma unroll
            for (int kd = 0; kd < 3; kd++) {
                int dd = d + kd - 1;
                if (dd < 0 || dd >= DD) continue;
                #pragma unroll
                for (int kh = 0; kh < 3; kh++) {
                    int hh = h + kh - 1;
                    if (hh < 0 || hh >= 8) continue;
                    #pragma unroll
                    for (int kw = 0; kw < 3; kw++) {
                        int ww2 = w + kw - 1;
                        if (ww2 < 0 || ww2 >= 8) continue;
                        v += xs[dd * 64 + hh * 8 + ww2] * w1s[o * 27 + kd * 9 + kh * 3 + kw];
                    }
                }
            }
            y1s[r] = fmaxf(v, 0.0f);
        }
        __syncthreads();
        {
            int kd0 = half * 10;
            for (int kd = kd0; kd < kd0 + 10; kd++) {
                #pragma unroll
                for (int kh = 0; kh < 3; kh++) {
                    int hh = oh + kh - 1;
                    if (hh < 0 || hh >= 8) continue;
                    #pragma unroll
                    for (int kw = 0; kw < 3; kw++) {
                        int ww2 = ow + kw - 1;
                        if (ww2 < 0 || ww2 >= 8) continue;
                        acc2 += y1s[kd * 64 + hh * 8 + ww2] * w2s[o * 180 + kd * 9 + kh * 3 + kw];
                    }
                }
            }
        }
        __syncthreads();
    }
    accs[tid] = acc2;
    __syncthreads();
    if (tid < 64) {
        float v = accs[tid] + accs[tid + 64] + c2b[0];
        g_flat[b * 64 + tid] = fmaxf(v, 0.0f);
    }
}

// ---------------- gating: top-1 argmax, lists, aux loss ----------------
__global__ void gate_kernel(const float* __restrict__ w_gate,
                            float* __restrict__ aux_out, int write_aux) {
    __shared__ int cnt_s[NE];
    int b = threadIdx.x;                        // 128 threads, 1 block
    if (b < NE) cnt_s[b] = 0;
    __syncthreads();

    float lg[NE] = {0.f, 0.f, 0.f, 0.f};
    for (int i = 0; i < IN_DIM; i++) {
        float f = g_flat[b * IN_DIM + i];
        #pragma unroll
        for (int e = 0; e < NE; e++) lg[e] += f * w_gate[i * NE + e];
    }
    int best = 0; float bv = lg[0];
    #pragma unroll
    for (int e = 1; e < NE; e++) if (lg[e] > bv) { bv = lg[e]; best = e; }
    g_expert[b] = best;
    int pos = atomicAdd(&cnt_s[best], 1);
    g_list[best * BB + pos] = b;
    __syncthreads();
    if (b < NE) g_cnt[b] = cnt_s[b];
    if (b == 0) {
        float m = 0.f;
        for (int e = 0; e < NE; e++) m += (float)cnt_s[e];
        m *= 0.25f;
        float var = 0.f;
        for (int e = 0; e < NE; e++) {
            float d = (float)cnt_s[e] - m;
            var += d * d;
        }
        var *= (1.0f / 3.0f);                   // ddof=1
        float aux = 2.0f * (var / (m * m + 1e-10f)) * 1e-2f;
        if (write_aux) aux_out[0] = aux;
    }
}

// --------- expert layer 1 (j-split): H = relu(flat @ w1[e] + b1[e]) ----------
__global__ void expert_l1(const float* __restrict__ w1,
                          const float* __restrict__ b1) {
    int b = blockIdx.x;
    int j0 = blockIdx.y * L1COLS;
    int tid = threadIdx.x;                      // 128 threads
    __shared__ float fs[IN_DIM];
    if (tid < IN_DIM) fs[tid] = g_flat[b * IN_DIM + tid];
    __syncthreads();
    int e = g_expert[b];
    const float* w1e = w1 + (size_t)e * IN_DIM * HID + j0 + tid;
    float acc[L1COLS / 128];
    #pragma unroll
    for (int jj = 0; jj < L1COLS / 128; jj++)
        acc[jj] = b1[e * HID + j0 + jj * 128 + tid];
    for (int i = 0; i < IN_DIM; i++) {
        float f = fs[i];
        const float* row = w1e + (size_t)i * HID;
        #pragma unroll
        for (int jj = 0; jj < L1COLS / 128; jj++)
            acc[jj] = fmaf(f, row[jj * 128], acc[jj]);
    }
    #pragma unroll
    for (int jj = 0; jj < L1COLS / 128; jj++)
        g_H[(size_t)b * HID + j0 + jj * 128 + tid] = fmaxf(acc[jj], 0.0f);
}

// ------ expert layer 2: j-lane-packed FFMA2, hs broadcast, K-split ------
// Lanes of each f32x2 = two ADJACENT j columns (w2 float2 load, no MOV).
// hs stored pre-duplicated (u64, both halves equal) -> one broadcast LDS.64
// feeds TWO j-pairs per thread: LDS wavefronts per MAC halved vs sample-lane
// packing. grid = (HID/JBLK, NE*NCHUNK, KS).
__global__ void __launch_bounds__(128) expert_l2(const float* __restrict__ w2) {
    int e = blockIdx.y / NCHUNK;
    int chunk = blockIdx.y % NCHUNK;
    int ks = blockIdx.z;
    int cnt = g_cnt[e];
    int s0 = chunk * CHUNK;
    if (s0 >= cnt) return;
    int ns = min(CHUNK, cnt - s0);
    int t = threadIdx.x;
    int jA = blockIdx.x * JBLK + 2 * t;         // pair A: columns jA, jA+1
    // pair B: columns jA+256, jA+257

    __shared__ int sid[CHUNK];
    __shared__ __align__(16) unsigned long long hs2[2][32][CHUNK + 1];

    if (t < CHUNK)
        sid[t] = (t < ns) ? g_list[e * BB + s0 + t] : 0;
    __syncthreads();

    unsigned long long accA[CHUNK], accB[CHUNK];
    #pragma unroll
    for (int s = 0; s < CHUNK; s++) { accA[s] = 0ULL; accB[s] = 0ULL; }

    const float* w2eA = w2 + (size_t)e * HID * HID + jA;
    const float* w2eB = w2eA + 256;
    const int hbase = ks * SEG;
    const int NTILES = SEG / 32;                // 8

    // fill: CHUNK samples x 8 float4 loads, duplicated into u64 lanes
    auto fill_tile = [&](int buf, int h0) {
        for (int idx = t; idx < CHUNK * 8; idx += 128) {
            int si = idx >> 3, q = idx & 7;
            float4 v = make_float4(0.f, 0.f, 0.f, 0.f);
            if (si < ns)
                v = *reinterpret_cast<const float4*>(
                        &g_H[(size_t)sid[si] * HID + h0 + q * 4]);
            int hh = q * 4;
            hs2[buf][hh + 0][si] = pack2(v.x, v.x);
            hs2[buf][hh + 1][si] = pack2(v.y, v.y);
            hs2[buf][hh + 2][si] = pack2(v.z, v.z);
            hs2[buf][hh + 3][si] = pack2(v.w, v.w);
        }
    };

    fill_tile(0, hbase);
    __syncthreads();

    for (int tt = 0; tt < NTILES; tt++) {
        int cur = tt & 1, nxt = cur ^ 1;
        if (tt + 1 < NTILES) fill_tile(nxt, hbase + (tt + 1) * 32);
        const float* wpA = w2eA + (size_t)(hbase + tt * 32) * HID;
        const float* wpB = w2eB + (size_t)(hbase + tt * 32) * HID;
        #pragma unroll
        for (int g = 0; g < 4; g++) {
            unsigned long long wa[8], wb[8];    // batch loads: MLP=16
            #pragma unroll
            for (int u = 0; u < 8; u++) {
                wa[u] = *reinterpret_cast<const unsigned long long*>(
                            wpA + (size_t)(g * 8 + u) * HID);
                wb[u] = *reinterpret_cast<const unsigned long long*>(
                            wpB + (size_t)(g * 8 + u) * HID);
            }
            #pragma unroll
            for (int u = 0; u < 8; u++) {
                #pragma unroll
                for (int s = 0; s < CHUNK; s++) {
                    unsigned long long h = hs2[cur][g * 8 + u][s];
                    accA[s] = fma2(h, wa[u], accA[s]);
                    accB[s] = fma2(h, wb[u], accB[s]);
                }
            }
        }
        __syncthreads();
    }
    for (int s = 0; s < ns; s++) {
        float lo, hi;
        unpack2(accA[s], lo, hi);
        *reinterpret_cast<float2*>(&g_part[ks][sid[s]][jA]) = make_float2(lo, hi);
        unpack2(accB[s], lo, hi);
        *reinterpret_cast<float2*>(&g_part[ks][sid[s]][jA + 256]) = make_float2(lo, hi);
    }
}

// --- fused K-split reduce + bias + softmax + 64x64 transform + sigmoid ---
__global__ void transform_kernel(const float* __restrict__ input,
                                 const float* __restrict__ b2,
                                 float* __restrict__ out) {
    int b = blockIdx.x;
    int tid = threadIdx.x;                      // 256 threads
    __shared__ float ys[64 * 65];
    __shared__ float ins[DD * 64];
    __shared__ float red[8];

    int e = g_expert[b];
    const float* b2e = b2 + e * HID;

    float v[16];
    float mx = -3.4e38f;
    #pragma unroll
    for (int k = 0; k < 16; k++) {
        int idx = k * 256 + tid;
        float s = b2e[idx];
        #pragma unroll
        for (int ks = 0; ks < KS; ks++) s += g_part[ks][b][idx];
        v[k] = s;
        mx = fmaxf(mx, s);
    }
    #pragma unroll
    for (int o = 16; o; o >>= 1) mx = fmaxf(mx, __shfl_xor_sync(0xffffffffu, mx, o));
    if ((tid & 31) == 0) red[tid >> 5] = mx;
    __syncthreads();
    mx = red[0];
    #pragma unroll
    for (int k = 1; k < 8; k++) mx = fmaxf(mx, red[k]);
    __syncthreads();

    float sum = 0.f;
    #pragma unroll
    for (int k = 0; k < 16; k++) {
        float ev = expf(v[k] - mx);
        sum += ev;
        int idx = k * 256 + tid;
        int i = idx >> 6, jn = idx & 63;
        ys[i * 65 + jn] = ev;
    }
    #pragma unroll
    for (int o = 16; o; o >>= 1) sum += __shfl_xor_sync(0xffffffffu, sum, o);
    if ((tid & 31) == 0) red[tid >> 5] = sum;

    for (int idx = tid; idx < DD * 64; idx += 256)
        ins[idx] = input[b * DD * 64 + idx];
    __syncthreads();
    sum = 0.f;
    #pragma unroll
    for (int k = 0; k < 8; k++) sum += red[k];
    float inv = 1.0f / sum;

    for (int item = tid; item < DD * 64; item += 256) {
        int d = item >> 6, i = item & 63;
        float accv = 0.f;
        #pragma unroll 8
        for (int jn = 0; jn < 64; jn++)
            accv = fmaf(ys[i * 65 + jn], ins[d * 64 + jn], accv);
        accv *= inv;
        out[b * DD * 64 + item] = 1.0f / (1.0f + expf(-accv));
    }
}

// ---------------- launch ----------------
extern "C" void kernel_launch(void* const* d_in, const int* in_sizes, int n_in,
                              void* d_out, int out_size) {
    const float* input  = (const float*)d_in[0];
    const float* c1w    = (const float*)d_in[1];
    const float* c1b    = (const float*)d_in[2];
    const float* c2w    = (const float*)d_in[3];
    const float* c2b    = (const float*)d_in[4];
    const float* w_gate = (const float*)d_in[5];
    const float* w1     = (const float*)d_in[6];
    const float* b1     = (const float*)d_in[7];
    const float* w2     = (const float*)d_in[8];
    const float* b2     = (const float*)d_in[9];
    float* out = (float*)d_out;

    int main_elems = BB * DD * IN_DIM;          // 163840
    int write_aux = (out_size > main_elems) ? 1 : 0;

    conv_kernel<<<BB, 128>>>(input, c1w, c1b, c2w, c2b);
    gate_kernel<<<1, 128>>>(w_gate, out + main_elems, write_aux);
    dim3 g1(BB, L1SPLIT);
    expert_l1<<<g1, 128>>>(w1, b1);
    dim3 g2(HID / JBLK, NE * NCHUNK, KS);
    expert_l2<<<g2, 128>>>(w2);
    transform_kernel<<<BB, 256>>>(input, b2, out);
}